// round 6
// baseline (speedup 1.0000x reference)
#include <cuda_runtime.h>
#include <cstdint>

// Problem constants
#define NVOX   65536          // B*W*H*L = 2*32*32*32
#define DDIM   512
#define EHEADS 64
#define VOUT   16
#define NBLOCKS 256
#define TILE_M 128            // voxels per compute tile
#define MAX_TILES 576         // ceil((NVOX + 64*127)/TILE_M) bound
#define IDXBUF 73728          // padded index buffer capacity

// ---------------- scratch (device globals: no allocations allowed) ----------
__device__ int g_counts[EHEADS];
__device__ int g_cursor[EHEADS];
__device__ int g_idx[IDXBUF];
__device__ int g_tile_head[640];

// ---------------- f32x2 helpers (sm_103a packed fp32) ------------------------
__device__ __forceinline__ void fma2(unsigned long long& d,
                                     unsigned long long a,
                                     unsigned long long b) {
    asm("fma.rn.f32x2 %0, %1, %2, %0;" : "+l"(d) : "l"(a), "l"(b));
}
__device__ __forceinline__ unsigned long long pack2(float a, float b) {
    unsigned long long r;
    asm("mov.b64 %0, {%1, %2};" : "=l"(r) : "f"(a), "f"(b));
    return r;
}
__device__ __forceinline__ float unpack_sum(unsigned long long a) {
    float lo, hi;
    asm("mov.b64 {%0, %1}, %2;" : "=f"(lo), "=f"(hi) : "l"(a));
    return lo + hi;
}

// ---------------- K0: zero counts -------------------------------------------
__global__ void k0_zero() {
    if (threadIdx.x < EHEADS) g_counts[threadIdx.x] = 0;
}

// ---------------- K1: per-head histogram (256 blocks, 1 elem/thread) ---------
__global__ void k1_count(const int* __restrict__ btg,
                         const int* __restrict__ b2h) {
    __shared__ int bh_s[NBLOCKS];
    __shared__ int hist[EHEADS];
    int tid = threadIdx.x;
    bh_s[tid] = b2h[tid];
    if (tid < EHEADS) hist[tid] = 0;
    __syncthreads();
    int n = blockIdx.x * 256 + tid;
    atomicAdd(&hist[bh_s[btg[n]]], 1);
    __syncthreads();
    if (tid < EHEADS) atomicAdd(&g_counts[tid], hist[tid]);
}

// ---------------- K2: padded scan, cursors, tile map, pad fill ---------------
__global__ void k2_scan() {
    __shared__ int cnts[EHEADS];
    __shared__ int poff[EHEADS + 1];
    int tid = threadIdx.x;                // 128 threads
    if (tid < EHEADS) cnts[tid] = g_counts[tid];
    __syncthreads();
    if (tid == 0) {
        int run = 0;
        for (int h = 0; h < EHEADS; ++h) {
            poff[h] = run;
            run += ((cnts[h] + TILE_M - 1) / TILE_M) * TILE_M;
        }
        poff[EHEADS] = run;
    }
    __syncthreads();
    for (int t = tid; t < 640; t += 128) g_tile_head[t] = -1;
    __syncthreads();
    if (tid < EHEADS) {
        int h = tid;
        int start = poff[h];
        int end = poff[h + 1];
        g_cursor[h] = start;
        for (int t = start / TILE_M; t < end / TILE_M; ++t) g_tile_head[t] = h;
        for (int p = start + cnts[h]; p < end; ++p) g_idx[p] = -1;
    }
}

// ---------------- K3: scatter voxel indices (256 blocks, 1 elem/thread) ------
__global__ void k3_scatter(const int* __restrict__ btg,
                           const int* __restrict__ b2h) {
    __shared__ int bh_s[NBLOCKS];
    __shared__ int cnt[EHEADS];
    __shared__ int base_s[EHEADS];
    int tid = threadIdx.x;
    bh_s[tid] = b2h[tid];
    if (tid < EHEADS) cnt[tid] = 0;
    __syncthreads();
    int n = blockIdx.x * 256 + tid;
    int h = bh_s[btg[n]];
    int r = atomicAdd(&cnt[h], 1);
    __syncthreads();
    if (tid < EHEADS) base_s[tid] = atomicAdd(&g_cursor[tid], cnt[tid]);
    __syncthreads();
    g_idx[base_s[h] + r] = n;
}

// ---------------- K4: grouped head-GEMV, 8 lanes per voxel, f32x2 ------------
// CTA = 256 threads, tile = 128 voxels. 8 warps x 4 voxel-groups x 4 passes.
// x loads fully coalesced (group of 8 lanes reads consecutive float4s of one
// row -> each warp LDG = 4 full 128B lines). W broadcast from smem (quarter-
// warp reads 8 distinct float4, groups alias -> conflict-free).
__global__ __launch_bounds__(256, 3)
void k4_compute(const float* __restrict__ x,
                const float* __restrict__ Wh,
                const float* __restrict__ bh,
                float* __restrict__ out) {
    __shared__ __align__(16) float Ws[VOUT * DDIM];   // 32 KB, [v][d]
    __shared__ __align__(16) float bs[VOUT];

    int t = blockIdx.x;
    int head = g_tile_head[t];
    if (head < 0) return;

    // stage W[head] (8192 contiguous floats) and bias
    {
        const float4* src = (const float4*)(Wh + head * (VOUT * DDIM));
        float4* dst = (float4*)Ws;
#pragma unroll
        for (int i = 0; i < 8; ++i)
            dst[threadIdx.x + 256 * i] = src[threadIdx.x + 256 * i];
        if (threadIdx.x < VOUT) bs[threadIdx.x] = bh[head * VOUT + threadIdx.x];
    }
    __syncthreads();

    int warp = threadIdx.x >> 5;
    int lane = threadIdx.x & 31;
    int sub  = lane & 7;            // position within 8-lane group
    int grp  = lane >> 3;           // voxel group 0..3

    const ulonglong2* Ws2 = (const ulonglong2*)Ws;    // 16B units, row=128

#pragma unroll 1
    for (int pass = 0; pass < 4; ++pass) {
        int slot = pass * 32 + warp * 4 + grp;        // 0..127
        int vox = g_idx[t * TILE_M + slot];
        bool valid = vox >= 0;
        int voxc = valid ? vox : 0;

        const float4* xr = (const float4*)x + (size_t)voxc * (DDIM / 4) + sub;

        unsigned long long acc[VOUT];
#pragma unroll
        for (int v = 0; v < VOUT; ++v) acc[v] = 0ull;

        float4 xcur = xr[0];
        float4 xnxt = xr[8];

#pragma unroll 2
        for (int chunk = 0; chunk < 16; ++chunk) {
            float4 xv = xcur;
            xcur = xnxt;
            if (chunk < 14) xnxt = xr[(chunk + 2) * 8];

            unsigned long long xa = pack2(xv.x, xv.y);
            unsigned long long xb = pack2(xv.z, xv.w);
            const ulonglong2* wp = Ws2 + chunk * 8 + sub;
#pragma unroll
            for (int v = 0; v < VOUT; ++v) {
                ulonglong2 w = wp[v * (DDIM / 4)];    // broadcast LDS.128
                fma2(acc[v], xa, w.x);
                fma2(acc[v], xb, w.y);
            }
        }

        // reduce each v over the 8-lane group; keep only the quad this lane stores
        float o0 = 0.f, o1 = 0.f, o2 = 0.f, o3 = 0.f;
#pragma unroll
        for (int v = 0; v < VOUT; ++v) {
            float s = unpack_sum(acc[v]);
            s += __shfl_xor_sync(0xffffffffu, s, 1);
            s += __shfl_xor_sync(0xffffffffu, s, 2);
            s += __shfl_xor_sync(0xffffffffu, s, 4);
            if ((v >> 2) == (sub & 3)) {
                int r = v & 3;
                if (r == 0) o0 = s;
                else if (r == 1) o1 = s;
                else if (r == 2) o2 = s;
                else o3 = s;
            }
        }

        if (valid && sub < 4) {
            float4 bv = ((const float4*)bs)[sub];
            float4 o;
            o.x = o0 + bv.x; o.y = o1 + bv.y; o.z = o2 + bv.z; o.w = o3 + bv.w;
            ((float4*)out)[(size_t)vox * 4 + sub] = o;
        }
    }
}

// ---------------- launch ------------------------------------------------------
extern "C" void kernel_launch(void* const* d_in, const int* in_sizes, int n_in,
                              void* d_out, int out_size) {
    const int*   btg = (const int*)d_in[0];     // block_type_grid (65536)
    const float* x   = (const float*)d_in[1];   // x (65536*512)
    const float* Wh  = (const float*)d_in[2];   // W_heads (64*16*512)
    const float* bh  = (const float*)d_in[3];   // b_heads (64*16)
    const int*   b2h = (const int*)d_in[4];     // block2head (256)
    float* out = (float*)d_out;

    k0_zero<<<1, 64>>>();
    k1_count<<<256, 256>>>(btg, b2h);
    k2_scan<<<1, 128>>>();
    k3_scatter<<<256, 256>>>(btg, b2h);
    k4_compute<<<MAX_TILES, 256>>>(x, Wh, bh, out);
}

// round 7
// speedup vs baseline: 1.1147x; 1.1147x over previous
#include <cuda_runtime.h>
#include <cstdint>

// Problem constants
#define NVOX   65536          // B*W*H*L = 2*32*32*32
#define DDIM   512
#define EHEADS 64
#define VOUT   16
#define NBLOCKS 256
#define TILE_M 128            // voxels per compute tile
#define MAX_TILES 576         // ceil bound on sum ceil(cnt/128)
#define IDXBUF 73728          // 65536 + 64*127 rounded up

#define XSTRIDE 36            // floats per staged x row (144 B, bank-padded)
#define XBUF_FLOATS (TILE_M * XSTRIDE)   // 4608 floats per buffer
// smem floats: W 8192 + bias 16 + ridx 128 + 2 x-buffers 9216 = 17552
#define K4_SMEM_BYTES (17552 * 4)        // 70208 B -> 3 CTAs/SM

// ---------------- scratch (device globals: no allocations allowed) ----------
__device__ int g_counts[EHEADS];
__device__ int g_cursor[EHEADS];
__device__ int g_idx[IDXBUF];
__device__ int g_tile_head[MAX_TILES];

// ---------------- f32x2 helpers (sm_103a packed fp32) ------------------------
__device__ __forceinline__ void fma2(unsigned long long& d,
                                     unsigned long long a,
                                     unsigned long long b) {
    asm("fma.rn.f32x2 %0, %1, %2, %0;" : "+l"(d) : "l"(a), "l"(b));
}
__device__ __forceinline__ float unpack_sum(unsigned long long a) {
    float lo, hi;
    asm("mov.b64 {%0, %1}, %2;" : "=f"(lo), "=f"(hi) : "l"(a));
    return lo + hi;
}

// ---------------- cp.async helpers -------------------------------------------
__device__ __forceinline__ void cpa16(uint32_t dst_smem, const void* src) {
    asm volatile("cp.async.ca.shared.global [%0], [%1], 16;"
                 :: "r"(dst_smem), "l"(src));
}
__device__ __forceinline__ void cpa_commit() {
    asm volatile("cp.async.commit_group;");
}
template <int N>
__device__ __forceinline__ void cpa_wait() {
    asm volatile("cp.async.wait_group %0;" :: "n"(N));
}

// ---------------- K1: per-head histogram (int4, grid 64) ---------------------
__global__ void k1_count(const int* __restrict__ btg,
                         const int* __restrict__ b2h) {
    __shared__ int bh_s[NBLOCKS];
    __shared__ int hist[EHEADS];
    int tid = threadIdx.x;
    bh_s[tid] = b2h[tid];
    if (tid < EHEADS) hist[tid] = 0;
    __syncthreads();
    int4 q = ((const int4*)btg)[blockIdx.x * 256 + tid];
    atomicAdd(&hist[bh_s[q.x]], 1);
    atomicAdd(&hist[bh_s[q.y]], 1);
    atomicAdd(&hist[bh_s[q.z]], 1);
    atomicAdd(&hist[bh_s[q.w]], 1);
    __syncthreads();
    if (tid < EHEADS) atomicAdd(&g_counts[tid], hist[tid]);
}

// ---------------- K2: scan + zero counts + tile map + pad fill ---------------
__global__ void k2_scan() {
    __shared__ int cnts[EHEADS];
    __shared__ int poff[EHEADS + 1];
    int tid = threadIdx.x;                // 256 threads
    if (tid < EHEADS) {
        cnts[tid] = g_counts[tid];
        g_counts[tid] = 0;                // reset for next graph replay
    }
    __syncthreads();
    if (tid == 0) {
        int run = 0;
        for (int h = 0; h < EHEADS; ++h) {
            poff[h] = run;
            run += ((cnts[h] + TILE_M - 1) / TILE_M) * TILE_M;
        }
        poff[EHEADS] = run;
    }
    __syncthreads();
    for (int t = tid; t < MAX_TILES; t += 256) g_tile_head[t] = -1;
    __syncthreads();
    if (tid < EHEADS) {
        int h = tid;
        int start = poff[h];
        int end = poff[h + 1];
        g_cursor[h] = start;
        for (int t = start / TILE_M; t < end / TILE_M; ++t) g_tile_head[t] = h;
        for (int p = start + cnts[h]; p < end; ++p) g_idx[p] = -1;
    }
}

// ---------------- K3: scatter voxel indices (int4, grid 64) ------------------
__global__ void k3_scatter(const int* __restrict__ btg,
                           const int* __restrict__ b2h) {
    __shared__ int bh_s[NBLOCKS];
    __shared__ int cnt[EHEADS];
    __shared__ int base_s[EHEADS];
    int tid = threadIdx.x;
    bh_s[tid] = b2h[tid];
    if (tid < EHEADS) cnt[tid] = 0;
    __syncthreads();
    int gid = blockIdx.x * 256 + tid;
    int4 q = ((const int4*)btg)[gid];
    int h0 = bh_s[q.x], h1 = bh_s[q.y], h2 = bh_s[q.z], h3 = bh_s[q.w];
    int r0 = atomicAdd(&cnt[h0], 1);
    int r1 = atomicAdd(&cnt[h1], 1);
    int r2 = atomicAdd(&cnt[h2], 1);
    int r3 = atomicAdd(&cnt[h3], 1);
    __syncthreads();
    if (tid < EHEADS) base_s[tid] = atomicAdd(&g_cursor[tid], cnt[tid]);
    __syncthreads();
    int n = gid * 4;
    g_idx[base_s[h0] + r0] = n;
    g_idx[base_s[h1] + r1] = n + 1;
    g_idx[base_s[h2] + r2] = n + 2;
    g_idx[base_s[h3] + r3] = n + 3;
}

// ---------------- no-op spacers (so ncu -s 5 -c 1 lands on k4) ---------------
__global__ void k_nop() {}

// ---------------- K4: grouped head-GEMV, lane-per-voxel, cp.async staged x ---
// CTA = 128 threads = 128 voxels. W[head] (32 KB) broadcast from smem.
// x streamed through a double-buffered smem stage: coalesced LDGSTS writes
// (8 lanes per row -> 4 x 128B lines per instr), bank-padded 144B rows so the
// lane-per-voxel LDS.128 reads are conflict-free. Accumulate in f32x2.
__global__ __launch_bounds__(128, 3)
void k4_compute(const float* __restrict__ x,
                const float* __restrict__ Wh,
                const float* __restrict__ bh,
                float* __restrict__ out) {
    extern __shared__ float smem[];
    float* Ws   = smem;                        // 8192 floats
    float* bs   = smem + 8192;                 // 16 floats
    int*   ridx = (int*)(smem + 8208);         // 128 ints
    float* xb0  = smem + 8336;                 // 4608 floats (16B aligned)
    float* xb1  = xb0 + XBUF_FLOATS;           // 4608 floats

    int t = blockIdx.x;
    int head = g_tile_head[t];
    if (head < 0) return;
    int tid = threadIdx.x;

    // voxel indices for this tile
    ridx[tid] = g_idx[t * TILE_M + tid];

    // group 0: W[head] (2048 float4) + bias via cp.async
    {
        const float4* wsrc = (const float4*)(Wh + head * (VOUT * DDIM));
        uint32_t wdst = (uint32_t)__cvta_generic_to_shared(Ws) + tid * 16;
#pragma unroll
        for (int i = 0; i < 16; ++i)
            cpa16(wdst + i * 2048, (const void*)(wsrc + tid + i * 128));
        if (tid < 4)
            cpa16((uint32_t)__cvta_generic_to_shared(bs) + tid * 16,
                  (const void*)((const float4*)(bh + head * VOUT) + tid));
    }
    cpa_commit();
    __syncthreads();                           // ridx visible to all

    // per-thread staging assignment: 8 rows x 1 float4 each per step
    int col4 = tid & 7;                        // float4 column 0..7
    int rowb = tid >> 3;                       // base row 0..15
    const float* srcrow[8];
#pragma unroll
    for (int k = 0; k < 8; ++k) {
        int v = ridx[rowb + 16 * k];
        if (v < 0) v = 0;                      // pad rows read row 0 (ignored)
        srcrow[k] = x + (size_t)v * DDIM + col4 * 4;
    }
    uint32_t xs0 = (uint32_t)__cvta_generic_to_shared(xb0);
    uint32_t xdst0 = xs0 + (rowb * XSTRIDE + col4 * 4) * 4;
    uint32_t xdst1 = xdst0 + XBUF_FLOATS * 4;

    // group 1: stage step 0
#pragma unroll
    for (int k = 0; k < 8; ++k)
        cpa16(xdst0 + k * (16 * XSTRIDE * 4), (const void*)srcrow[k]);
    cpa_commit();

    int voxme = ridx[tid];
    unsigned long long acc[VOUT];
#pragma unroll
    for (int v = 0; v < VOUT; ++v) acc[v] = 0ull;

    const ulonglong2* myrow0 = (const ulonglong2*)(xb0 + tid * XSTRIDE);
    const ulonglong2* myrow1 = (const ulonglong2*)(xb1 + tid * XSTRIDE);

#pragma unroll 1
    for (int s = 0; s < 16; ++s) {
        if (s + 1 < 16) {                      // stage step s+1 into other buf
            uint32_t nxt = ((s + 1) & 1) ? xdst1 : xdst0;
#pragma unroll
            for (int k = 0; k < 8; ++k)
                cpa16(nxt + k * (16 * XSTRIDE * 4),
                      (const void*)(srcrow[k] + (s + 1) * 32));
            cpa_commit();
            cpa_wait<1>();                     // step s (and W) complete
        } else {
            cpa_wait<0>();
        }
        __syncthreads();

        const ulonglong2* xr = (s & 1) ? myrow1 : myrow0;
        const ulonglong2* wp = (const ulonglong2*)Ws + s * 8;
#pragma unroll
        for (int j = 0; j < 8; ++j) {
            ulonglong2 xa = xr[j];             // 4 x floats, pre-paired
#pragma unroll
            for (int v = 0; v < VOUT; ++v) {
                ulonglong2 w = wp[j + v * 128];  // broadcast LDS.128
                fma2(acc[v], xa.x, w.x);
                fma2(acc[v], xa.y, w.y);
            }
        }
        __syncthreads();                       // before next overwrite
    }

    if (voxme >= 0) {
        float4* orow = (float4*)(out + (size_t)voxme * VOUT);
#pragma unroll
        for (int q = 0; q < 4; ++q) {
            float4 r;
            r.x = unpack_sum(acc[q * 4 + 0]) + bs[q * 4 + 0];
            r.y = unpack_sum(acc[q * 4 + 1]) + bs[q * 4 + 1];
            r.z = unpack_sum(acc[q * 4 + 2]) + bs[q * 4 + 2];
            r.w = unpack_sum(acc[q * 4 + 3]) + bs[q * 4 + 3];
            orow[q] = r;
        }
    }
}

// ---------------- launch ------------------------------------------------------
extern "C" void kernel_launch(void* const* d_in, const int* in_sizes, int n_in,
                              void* d_out, int out_size) {
    const int*   btg = (const int*)d_in[0];     // block_type_grid (65536)
    const float* x   = (const float*)d_in[1];   // x (65536*512)
    const float* Wh  = (const float*)d_in[2];   // W_heads (64*16*512)
    const float* bh  = (const float*)d_in[3];   // b_heads (64*16)
    const int*   b2h = (const int*)d_in[4];     // block2head (256)
    float* out = (float*)d_out;

    cudaFuncSetAttribute(k4_compute,
                         cudaFuncAttributeMaxDynamicSharedMemorySize,
                         K4_SMEM_BYTES);

    k1_count<<<64, 256>>>(btg, b2h);
    k2_scan<<<1, 256>>>();
    k3_scatter<<<64, 256>>>(btg, b2h);
    k_nop<<<1, 32>>>();
    k_nop<<<1, 32>>>();   // ncu -s 5 -c 1 now lands on k4_compute
    k4_compute<<<MAX_TILES, 128, K4_SMEM_BYTES>>>(x, Wh, bh, out);
}

// round 9
// speedup vs baseline: 1.5942x; 1.4301x over previous
#include <cuda_runtime.h>
#include <cstdint>

// Problem constants
#define DDIM   512
#define EHEADS 64
#define VOUT   16
#define NBLOCKS 256
#define TILE_M 128
#define CAP    8192                 // per-head slot capacity (64 tiles)
#define TPH    (CAP / TILE_M)       // 64 tiles per head
#define XSTRIDE 36                  // floats per staged x row (144B)
#define XBUF   (TILE_M * XSTRIDE)   // 4608 floats per buffer
// smem floats: W 8192 + bias 16 + ridx 128 + 2 x-buffers 9216 = 17552
#define K4_SMEM_BYTES (17552 * 4)   // 70208 B -> 3 CTAs/SM

// ---------------- scratch (device globals: no allocations allowed) ----------
__device__ int g_cursor[EHEADS];          // cleared each replay by k0
__device__ int g_idx[EHEADS * CAP];       // fixed-capacity head buckets

// ---------------- f32x2 helpers ----------------------------------------------
__device__ __forceinline__ void fma2(unsigned long long& d,
                                     unsigned long long a,
                                     unsigned long long b) {
    asm("fma.rn.f32x2 %0, %1, %2, %0;" : "+l"(d) : "l"(a), "l"(b));
}
__device__ __forceinline__ float unpack_sum(unsigned long long a) {
    float lo, hi;
    asm("mov.b64 {%0, %1}, %2;" : "=f"(lo), "=f"(hi) : "l"(a));
    return lo + hi;
}

// ---------------- cp.async helpers -------------------------------------------
__device__ __forceinline__ void cpa16(uint32_t dst_smem, const void* src) {
    asm volatile("cp.async.ca.shared.global [%0], [%1], 16;"
                 :: "r"(dst_smem), "l"(src));
}
__device__ __forceinline__ void cpa_commit() {
    asm volatile("cp.async.commit_group;");
}
template <int N>
__device__ __forceinline__ void cpa_wait() {
    asm volatile("cp.async.wait_group %0;" :: "n"(N));
}
__device__ __forceinline__ uint32_t s2u(const void* p) {
    return (uint32_t)__cvta_generic_to_shared(p);
}

// ---------------- K0: zero cursors -------------------------------------------
__global__ void k0_zero() { g_cursor[threadIdx.x] = 0; }

// ---------------- KS: scatter into fixed-capacity head buckets ---------------
__global__ void kS_scatter(const int* __restrict__ btg,
                           const int* __restrict__ b2h) {
    __shared__ int bh_s[NBLOCKS];
    __shared__ int cnt[EHEADS];
    __shared__ int base_s[EHEADS];
    int tid = threadIdx.x;
    bh_s[tid] = b2h[tid];
    if (tid < EHEADS) cnt[tid] = 0;
    __syncthreads();
    int gid = blockIdx.x * 256 + tid;
    int4 q = ((const int4*)btg)[gid];
    int h0 = bh_s[q.x], h1 = bh_s[q.y], h2 = bh_s[q.z], h3 = bh_s[q.w];
    int r0 = atomicAdd(&cnt[h0], 1);
    int r1 = atomicAdd(&cnt[h1], 1);
    int r2 = atomicAdd(&cnt[h2], 1);
    int r3 = atomicAdd(&cnt[h3], 1);
    __syncthreads();
    if (tid < EHEADS) base_s[tid] = atomicAdd(&g_cursor[tid], cnt[tid]);
    __syncthreads();
    int n = gid * 4;
    g_idx[h0 * CAP + base_s[h0] + r0] = n;
    g_idx[h1 * CAP + base_s[h1] + r1] = n + 1;
    g_idx[h2 * CAP + base_s[h2] + r2] = n + 2;
    g_idx[h3 * CAP + base_s[h3] + r3] = n + 3;
}

// ---------------- K4: grouped head-GEMV, 4vox x 4v register tile -------------
// CTA = 128 threads, tile = 128 voxels of one head. Static tile map:
// head = blockIdx.x>>6, slot base = (blockIdx.x&63)*128; empty tiles exit.
// Thread (w,vgrp,voxgrp): voxels w*32 + m*8 + voxgrp (m=0..3), outputs
// vgrp*4..+3. x staged via double-buffered cp.async (32 d per step),
// stride-36 rows so x-LDS phases are bank-conflict-free. d-paired f32x2.
__global__ __launch_bounds__(128)
void k4_compute(const float* __restrict__ x,
                const float* __restrict__ Wh,
                const float* __restrict__ bh,
                float* __restrict__ out) {
    extern __shared__ float smem[];
    float* Ws  = smem;                       // 8192 floats [v][d]
    float* bs  = smem + 8192;                // 16 floats
    int*  ridx = (int*)(smem + 8208);        // 128 ints
    float* xb0 = smem + 8336;                // 4608 floats
    // xb1 = xb0 + XBUF

    int head  = blockIdx.x >> 6;
    int sbase = (blockIdx.x & (TPH - 1)) * TILE_M;
    int cnt = g_cursor[head];
    if (sbase >= cnt) return;
    int tid = threadIdx.x;

    // group 0: W[head] (2048 float4) + bias via cp.async
    {
        const float4* wsrc = (const float4*)(Wh + head * (VOUT * DDIM));
        uint32_t wdst = s2u(Ws) + tid * 16;
#pragma unroll
        for (int i = 0; i < 16; ++i)
            cpa16(wdst + i * 2048, (const void*)(wsrc + tid + i * 128));
        if (tid < 4)
            cpa16(s2u(bs) + tid * 16,
                  (const void*)((const float4*)(bh + head * VOUT) + tid));
    }
    cpa_commit();

    int slot = sbase + tid;
    ridx[tid] = (slot < cnt) ? g_idx[head * CAP + slot] : -1;
    __syncthreads();

    // staging assignment: thread (rowb=tid>>3, c4=tid&7) stages rows rowb+16k
    int c4 = tid & 7;
    int rowb = tid >> 3;
    const float* srcrow[8];
#pragma unroll
    for (int k = 0; k < 8; ++k) {
        int v = ridx[rowb + 16 * k];
        if (v < 0) v = 0;                    // pad rows fetch row 0 (ignored)
        srcrow[k] = x + (size_t)v * DDIM + c4 * 4;
    }
    uint32_t xd0 = s2u(xb0) + (rowb * XSTRIDE + c4 * 4) * 4;
    uint32_t xd1 = xd0 + XBUF * 4;

    // group 1: stage step 0
#pragma unroll
    for (int k = 0; k < 8; ++k)
        cpa16(xd0 + k * (16 * XSTRIDE * 4), (const void*)srcrow[k]);
    cpa_commit();

    int lane = tid & 31, w = tid >> 5;
    int vgrp = lane >> 3, voxgrp = lane & 7;
    const float* myx0 = xb0 + (w * 32 + voxgrp) * XSTRIDE;
    const float* myW  = Ws + vgrp * 4 * DDIM;

    unsigned long long acc[16];
#pragma unroll
    for (int i = 0; i < 16; ++i) acc[i] = 0ull;

#pragma unroll 1
    for (int s = 0; s < 16; ++s) {
        if (s < 15) {                        // prefetch step s+1 (other buffer)
            uint32_t nxt = ((s + 1) & 1) ? xd1 : xd0;
            int boff = (s + 1) * 32;
#pragma unroll
            for (int k = 0; k < 8; ++k)
                cpa16(nxt + k * (16 * XSTRIDE * 4),
                      (const void*)(srcrow[k] + boff));
            cpa_commit();
            cpa_wait<1>();                   // step s (and W) complete
        } else {
            cpa_wait<0>();
        }
        __syncthreads();

        const float* xbase = (s & 1) ? (myx0 + XBUF) : myx0;
        const float* wb = myW + s * 32;
#pragma unroll
        for (int c = 0; c < 8; ++c) {        // 4-d chunks within the step
            ulonglong2 xf[4];
#pragma unroll
            for (int m = 0; m < 4; ++m)      // 4 voxels, rows strided by 8
                xf[m] = *(const ulonglong2*)(xbase + m * (8 * XSTRIDE) + c * 4);
#pragma unroll
            for (int vv = 0; vv < 4; ++vv) {
                ulonglong2 wf = *(const ulonglong2*)(wb + vv * DDIM + c * 4);
#pragma unroll
                for (int m = 0; m < 4; ++m) {
                    fma2(acc[vv * 4 + m], xf[m].x, wf.x);
                    fma2(acc[vv * 4 + m], xf[m].y, wf.y);
                }
            }
        }
        __syncthreads();                     // before buffer reuse
    }

    float4 bv = *(const float4*)(bs + vgrp * 4);
#pragma unroll
    for (int m = 0; m < 4; ++m) {
        int vox = ridx[w * 32 + m * 8 + voxgrp];
        if (vox >= 0) {
            float4 o;
            o.x = unpack_sum(acc[0 * 4 + m]) + bv.x;
            o.y = unpack_sum(acc[1 * 4 + m]) + bv.y;
            o.z = unpack_sum(acc[2 * 4 + m]) + bv.z;
            o.w = unpack_sum(acc[3 * 4 + m]) + bv.w;
            ((float4*)out)[(size_t)vox * 4 + vgrp] = o;
        }
    }
}

// ---------------- launch ------------------------------------------------------
extern "C" void kernel_launch(void* const* d_in, const int* in_sizes, int n_in,
                              void* d_out, int out_size) {
    const int*   btg = (const int*)d_in[0];     // block_type_grid (65536)
    const float* x   = (const float*)d_in[1];   // x (65536*512)
    const float* Wh  = (const float*)d_in[2];   // W_heads (64*16*512)
    const float* bh  = (const float*)d_in[3];   // b_heads (64*16)
    const int*   b2h = (const int*)d_in[4];     // block2head (256)
    float* out = (float*)d_out;

    cudaFuncSetAttribute(k4_compute,
                         cudaFuncAttributeMaxDynamicSharedMemorySize,
                         K4_SMEM_BYTES);

    k0_zero<<<1, EHEADS>>>();
    kS_scatter<<<64, 256>>>(btg, b2h);
    k4_compute<<<EHEADS * TPH, 128, K4_SMEM_BYTES>>>(x, Wh, bh, out);
    // 3 launches/iter: ncu -s 5 -c 1 lands on iteration-2's k4_compute
}

// round 11
// speedup vs baseline: 1.7347x; 1.0881x over previous
#include <cuda_runtime.h>
#include <cstdint>

// Problem constants
#define DDIM   512
#define EHEADS 64
#define VOUT   16
#define NBLOCKS 256
#define TILE_M 256                  // voxels per compute CTA (256 threads)
#define CAP    8192                 // per-head slot capacity
#define TPH    (CAP / TILE_M)       // 32 tiles per head
#define XSTRIDE 36                  // floats per staged x row (144B, bank-padded)
#define XBUF   (TILE_M * XSTRIDE)   // 9216 floats per buffer
// smem floats: W 8192 + bias 16 + ridx 256 + 2 x-buffers 18432 = 26896
#define K4_SMEM_BYTES (26896 * 4)   // 107584 B -> 2 CTAs/SM, single wave

// ---------------- scratch (device globals: no allocations allowed) ----------
__device__ int g_cursor[EHEADS];
__device__ int g_idx[EHEADS * CAP];

// ---------------- f32x2 helpers ----------------------------------------------
__device__ __forceinline__ void fma2(unsigned long long& d,
                                     unsigned long long a,
                                     unsigned long long b) {
    asm("fma.rn.f32x2 %0, %1, %2, %0;" : "+l"(d) : "l"(a), "l"(b));
}
__device__ __forceinline__ float unpack_sum(unsigned long long a) {
    float lo, hi;
    asm("mov.b64 {%0, %1}, %2;" : "=f"(lo), "=f"(hi) : "l"(a));
    return lo + hi;
}

// ---------------- cp.async helpers -------------------------------------------
__device__ __forceinline__ void cpa16(uint32_t dst_smem, const void* src) {
    asm volatile("cp.async.ca.shared.global [%0], [%1], 16;"
                 :: "r"(dst_smem), "l"(src));
}
__device__ __forceinline__ void cpa_commit() {
    asm volatile("cp.async.commit_group;");
}
template <int N>
__device__ __forceinline__ void cpa_wait() {
    asm volatile("cp.async.wait_group %0;" :: "n"(N));
}
__device__ __forceinline__ uint32_t s2u(const void* p) {
    return (uint32_t)__cvta_generic_to_shared(p);
}

// ---------------- K0: zero cursors -------------------------------------------
__global__ void k0_zero() { g_cursor[threadIdx.x] = 0; }

// ---------------- KS: scatter into fixed-capacity head buckets ---------------
__global__ void kS_scatter(const int* __restrict__ btg,
                           const int* __restrict__ b2h) {
    __shared__ int bh_s[NBLOCKS];
    __shared__ int cnt[EHEADS];
    __shared__ int base_s[EHEADS];
    int tid = threadIdx.x;
    bh_s[tid] = b2h[tid];
    if (tid < EHEADS) cnt[tid] = 0;
    __syncthreads();
    int gid = blockIdx.x * 256 + tid;
    int4 q = ((const int4*)btg)[gid];
    int h0 = bh_s[q.x], h1 = bh_s[q.y], h2 = bh_s[q.z], h3 = bh_s[q.w];
    int r0 = atomicAdd(&cnt[h0], 1);
    int r1 = atomicAdd(&cnt[h1], 1);
    int r2 = atomicAdd(&cnt[h2], 1);
    int r3 = atomicAdd(&cnt[h3], 1);
    __syncthreads();
    if (tid < EHEADS) base_s[tid] = atomicAdd(&g_cursor[tid], cnt[tid]);
    __syncthreads();
    int n = gid * 4;
    g_idx[h0 * CAP + base_s[h0] + r0] = n;
    g_idx[h1 * CAP + base_s[h1] + r1] = n + 1;
    g_idx[h2 * CAP + base_s[h2] + r2] = n + 2;
    g_idx[h3 * CAP + base_s[h3] + r3] = n + 3;
}

// ---------------- spacer so ncu capture (launch #4) lands on k4 --------------
__global__ void k_nop() {}

// ---------------- K4: grouped head-GEMV, 4vox x 4v, conflict-free W ----------
// CTA = 256 threads = 256 voxels of one head, single wave chip-wide (occ 2).
// W stored [d-chunk][vv][vgrp] in float4 units so the 4 distinct per-warp W
// addresses are 16B-consecutive -> conflict-free single-wavefront LDS.128.
// x double-buffered via cp.async (32 d per step), rows padded to 144B.
__global__ __launch_bounds__(256, 2)
void k4_compute(const float* __restrict__ x,
                const float* __restrict__ Wh,
                const float* __restrict__ bh,
                float* __restrict__ out) {
    extern __shared__ float smem[];
    float* Ws  = smem;                       // 8192 floats, float4[cc*16+vv*4+vgrp]
    float* bs  = smem + 8192;                // 16 floats
    int*  ridx = (int*)(smem + 8208);        // 256 ints
    float* xb0 = smem + 8464;                // 9216 floats (16B aligned)
    // xb1 = xb0 + XBUF

    int head  = blockIdx.x >> 5;             // TPH = 32
    int sbase = (blockIdx.x & (TPH - 1)) * TILE_M;
    int cnt = g_cursor[head];
    if (sbase >= cnt) return;
    int tid = threadIdx.x;

    // group 0: W[head] into interleaved layout + bias, via cp.async.
    // thread t stages v = t>>4, chunks cc = (t&15)*8 + i.
    {
        const float* wsrc = Wh + head * (VOUT * DDIM);
        int v  = tid >> 4;
        int cb = (tid & 15) * 8;
        uint32_t wbase = s2u(Ws);
        int dsub = (v & 3) * 4 + (v >> 2);   // vv*4 + vgrp
#pragma unroll
        for (int i = 0; i < 8; ++i) {
            int cc = cb + i;
            cpa16(wbase + (cc * 16 + dsub) * 16,
                  (const void*)(wsrc + v * DDIM + cc * 4));
        }
        if (tid < 4)
            cpa16(s2u(bs) + tid * 16,
                  (const void*)((const float4*)(bh + head * VOUT) + tid));
    }
    cpa_commit();

    int slot = sbase + tid;
    ridx[tid] = (slot < cnt) ? g_idx[head * CAP + slot] : -1;
    __syncthreads();

    // x staging: thread (rowb=tid>>3, c4=tid&7) stages rows rowb+32k, k=0..7
    int c4 = tid & 7;
    int rowb = tid >> 3;
    const float* srcrow[8];
#pragma unroll
    for (int k = 0; k < 8; ++k) {
        int v = ridx[rowb + 32 * k];
        if (v < 0) v = 0;                    // pad rows fetch row 0 (ignored)
        srcrow[k] = x + (size_t)v * DDIM + c4 * 4;
    }
    uint32_t xd0 = s2u(xb0) + (rowb * XSTRIDE + c4 * 4) * 4;
    uint32_t xd1 = xd0 + XBUF * 4;

    // group 1: stage step 0
#pragma unroll
    for (int k = 0; k < 8; ++k)
        cpa16(xd0 + k * (32 * XSTRIDE * 4), (const void*)srcrow[k]);
    cpa_commit();

    int lane = tid & 31, w = tid >> 5;       // 8 warps
    int vgrp = lane >> 3, voxgrp = lane & 7;
    const float* myx0 = xb0 + (w * 32 + voxgrp) * XSTRIDE;
    const float4* Ws4 = (const float4*)Ws;

    unsigned long long acc[16];
#pragma unroll
    for (int i = 0; i < 16; ++i) acc[i] = 0ull;

#pragma unroll 1
    for (int s = 0; s < 16; ++s) {
        if (s < 15) {                        // prefetch step s+1 (other buffer)
            uint32_t nxt = ((s + 1) & 1) ? xd1 : xd0;
            int boff = (s + 1) * 32;
#pragma unroll
            for (int k = 0; k < 8; ++k)
                cpa16(nxt + k * (32 * XSTRIDE * 4),
                      (const void*)(srcrow[k] + boff));
            cpa_commit();
            cpa_wait<1>();                   // step s (and W) complete
        } else {
            cpa_wait<0>();
        }
        __syncthreads();

        const float* xbase = (s & 1) ? (myx0 + XBUF) : myx0;
#pragma unroll
        for (int c = 0; c < 8; ++c) {        // 4-d chunks within the step
            int cc = s * 8 + c;
            ulonglong2 xf[4];
#pragma unroll
            for (int m = 0; m < 4; ++m)      // 4 voxels, rows strided by 8
                xf[m] = *(const ulonglong2*)(xbase + m * (8 * XSTRIDE) + c * 4);
#pragma unroll
            for (int vv = 0; vv < 4; ++vv) {
                float4 wq = Ws4[cc * 16 + vv * 4 + vgrp];  // conflict-free
                ulonglong2 wf = *(const ulonglong2*)&wq;
#pragma unroll
                for (int m = 0; m < 4; ++m) {
                    fma2(acc[vv * 4 + m], xf[m].x, wf.x);
                    fma2(acc[vv * 4 + m], xf[m].y, wf.y);
                }
            }
        }
        __syncthreads();                     // before buffer reuse
    }

    float4 bv = *(const float4*)(bs + vgrp * 4);
#pragma unroll
    for (int m = 0; m < 4; ++m) {
        int vox = ridx[w * 32 + m * 8 + voxgrp];
        if (vox >= 0) {
            float4 o;
            o.x = unpack_sum(acc[0 * 4 + m]) + bv.x;
            o.y = unpack_sum(acc[1 * 4 + m]) + bv.y;
            o.z = unpack_sum(acc[2 * 4 + m]) + bv.z;
            o.w = unpack_sum(acc[3 * 4 + m]) + bv.w;
            ((float4*)out)[(size_t)vox * 4 + vgrp] = o;
        }
    }
}

// ---------------- launch ------------------------------------------------------
extern "C" void kernel_launch(void* const* d_in, const int* in_sizes, int n_in,
                              void* d_out, int out_size) {
    const int*   btg = (const int*)d_in[0];     // block_type_grid (65536)
    const float* x   = (const float*)d_in[1];   // x (65536*512)
    const float* Wh  = (const float*)d_in[2];   // W_heads (64*16*512)
    const float* bh  = (const float*)d_in[3];   // b_heads (64*16)
    const int*   b2h = (const int*)d_in[4];     // block2head (256)
    float* out = (float*)d_out;

    cudaFuncSetAttribute(k4_compute,
                         cudaFuncAttributeMaxDynamicSharedMemorySize,
                         K4_SMEM_BYTES);

    k0_zero<<<1, EHEADS>>>();
    kS_scatter<<<64, 256>>>(btg, b2h);
    k_nop<<<1, 32>>>();   // ncu captures launch #4 -> k4_compute
    k4_compute<<<EHEADS * TPH, 256, K4_SMEM_BYTES>>>(x, Wh, bh, out);
}